// round 1
// baseline (speedup 1.0000x reference)
#include <cuda_runtime.h>
#include <math.h>

// Problem constants
#define B_TOT    16384
#define T_STEPS  5
#define H_DIM    256
#define GOAL_D   64
#define HID_D    1024
#define OUT_D    64
#define OBS_D    1280          // TIME_FRAME * OBS_PER_FRAME
#define SDIM     1344          // OBS_D + GOAL_D

// Scratch (device globals: allocation-free per harness rules)
__device__ float g_U [T_STEPS * B_TOT * H_DIM];   // 84 MB: input transforms (reused L0 then L1)
__device__ float g_Y [T_STEPS * B_TOT * H_DIM];   // 84 MB: per-step hidden outputs (reused L0 then L1)
__device__ float g_h1[B_TOT * HID_D];             // 64 MB
__device__ float g_h2[B_TOT * HID_D];             // 64 MB

enum AMode { A_PLAIN = 0, A_STATE = 1, A_CONCAT = 2 };
enum EpiMode { E_BIAS = 0, E_BIAS_RELU = 1, E_BIAS_TANH = 2, E_ADDU_TANH = 3 };

// C[m,n] = epilogue( sum_k A[m,k] * W[n,k] )
// A-modes:
//   A_PLAIN : A + m*lda
//   A_STATE : row m -> (t = m>>14, b = m&16383); src = state + b*SDIM + (4-t)*H_DIM  (time reversal)
//   A_CONCAT: k<256 from A (lda=256), k>=256 from A2 + m*SDIM + (k-256)   (goal columns of state)
// W is [N][K] row-major (ldw == K). Epilogues per EpiMode; bias2 optional (nullptr).
template<int BM, int BN, int BK, int AMODE, int EPI>
__global__ __launch_bounds__(256, 2)
void gemm_nt(const float* __restrict__ A, int lda,
             const float* __restrict__ A2,
             const float* __restrict__ W,
             const float* __restrict__ bias1,
             const float* __restrict__ bias2,
             const float* __restrict__ U,
             float* __restrict__ C,
             int M, int N, int K)
{
    constexpr int RM = BM / 64;   // row groups (4 rows each per thread)
    constexpr int CN = BN / 64;   // col groups

    __shared__ __align__(16) float As[BK][BM + 4];
    __shared__ __align__(16) float Ws[BK][BN + 4];

    const int tid = threadIdx.x;
    const int tx  = tid & 15;
    const int ty  = tid >> 4;
    const int m0  = blockIdx.y * BM;
    const int n0  = blockIdx.x * BN;

    float acc[RM * 4][CN * 4];
#pragma unroll
    for (int i = 0; i < RM * 4; ++i)
#pragma unroll
        for (int j = 0; j < CN * 4; ++j)
            acc[i][j] = 0.0f;

    for (int kt = 0; kt < K; kt += BK) {
        // ---- load A tile (transposed into As[k][m]) ----
        constexpr int AITER = (BM * BK) / (256 * 4);
#pragma unroll
        for (int it = 0; it < AITER; ++it) {
            const int r  = (tid >> 2) + it * 64;
            const int kc = (tid & 3) * 4;
            const int gk = kt + kc;
            float4 v;
            if (AMODE == A_PLAIN) {
                v = *reinterpret_cast<const float4*>(A + (size_t)(m0 + r) * lda + gk);
            } else if (AMODE == A_STATE) {
                const int m = m0 + r;
                const int b = m & (B_TOT - 1);
                const int t = m >> 14;
                v = *reinterpret_cast<const float4*>(A + (size_t)b * SDIM + (4 - t) * H_DIM + gk);
            } else { // A_CONCAT: k boundary (256) is BK-tile aligned, no straddle
                const int m = m0 + r;
                if (gk < H_DIM)
                    v = *reinterpret_cast<const float4*>(A + (size_t)m * lda + gk);
                else
                    v = *reinterpret_cast<const float4*>(A2 + (size_t)m * SDIM + (gk - H_DIM));
            }
            As[kc + 0][r] = v.x;
            As[kc + 1][r] = v.y;
            As[kc + 2][r] = v.z;
            As[kc + 3][r] = v.w;
        }
        // ---- load W tile (transposed into Ws[k][n]) ----
        constexpr int WITER = (BN * BK) / (256 * 4);
#pragma unroll
        for (int it = 0; it < WITER; ++it) {
            const int n  = (tid >> 2) + it * 64;
            const int kc = (tid & 3) * 4;
            float4 v = *reinterpret_cast<const float4*>(W + (size_t)(n0 + n) * K + kt + kc);
            Ws[kc + 0][n] = v.x;
            Ws[kc + 1][n] = v.y;
            Ws[kc + 2][n] = v.z;
            Ws[kc + 3][n] = v.w;
        }
        __syncthreads();

#pragma unroll
        for (int kk = 0; kk < BK; ++kk) {
            float af[RM * 4];
            float bf[CN * 4];
#pragma unroll
            for (int rg = 0; rg < RM; ++rg) {
                float4 a4 = *reinterpret_cast<const float4*>(&As[kk][rg * 64 + ty * 4]);
                af[rg * 4 + 0] = a4.x; af[rg * 4 + 1] = a4.y;
                af[rg * 4 + 2] = a4.z; af[rg * 4 + 3] = a4.w;
            }
#pragma unroll
            for (int cg = 0; cg < CN; ++cg) {
                float4 b4 = *reinterpret_cast<const float4*>(&Ws[kk][cg * 64 + tx * 4]);
                bf[cg * 4 + 0] = b4.x; bf[cg * 4 + 1] = b4.y;
                bf[cg * 4 + 2] = b4.z; bf[cg * 4 + 3] = b4.w;
            }
#pragma unroll
            for (int i = 0; i < RM * 4; ++i)
#pragma unroll
                for (int j = 0; j < CN * 4; ++j)
                    acc[i][j] = fmaf(af[i], bf[j], acc[i][j]);
        }
        __syncthreads();
    }

    // ---- epilogue (float4 stores) ----
#pragma unroll
    for (int rg = 0; rg < RM; ++rg) {
#pragma unroll
        for (int i = 0; i < 4; ++i) {
            const int m = m0 + rg * 64 + ty * 4 + i;
#pragma unroll
            for (int cg = 0; cg < CN; ++cg) {
                const int n = n0 + cg * 64 + tx * 4;
                float4 r;
                r.x = acc[rg * 4 + i][cg * 4 + 0];
                r.y = acc[rg * 4 + i][cg * 4 + 1];
                r.z = acc[rg * 4 + i][cg * 4 + 2];
                r.w = acc[rg * 4 + i][cg * 4 + 3];
                if (EPI == E_ADDU_TANH) {
                    float4 u4 = *reinterpret_cast<const float4*>(U + (size_t)m * N + n);
                    r.x = tanhf(r.x + u4.x);
                    r.y = tanhf(r.y + u4.y);
                    r.z = tanhf(r.z + u4.z);
                    r.w = tanhf(r.w + u4.w);
                } else {
                    float4 b4 = *reinterpret_cast<const float4*>(bias1 + n);
                    r.x += b4.x; r.y += b4.y; r.z += b4.z; r.w += b4.w;
                    if (bias2 != nullptr) {
                        float4 c4 = *reinterpret_cast<const float4*>(bias2 + n);
                        r.x += c4.x; r.y += c4.y; r.z += c4.z; r.w += c4.w;
                    }
                    if (EPI == E_BIAS_RELU) {
                        r.x = fmaxf(r.x, 0.0f); r.y = fmaxf(r.y, 0.0f);
                        r.z = fmaxf(r.z, 0.0f); r.w = fmaxf(r.w, 0.0f);
                    } else if (EPI == E_BIAS_TANH) {
                        r.x = tanhf(r.x); r.y = tanhf(r.y);
                        r.z = tanhf(r.z); r.w = tanhf(r.w);
                    }
                }
                *reinterpret_cast<float4*>(C + (size_t)m * N + n) = r;
            }
        }
    }
}

// Y = tanh(U) elementwise (first RNN step, h0 = 0)
__global__ void tanh_ew4(const float4* __restrict__ in, float4* __restrict__ out, int n4)
{
    int i = blockIdx.x * blockDim.x + threadIdx.x;
    if (i < n4) {
        float4 v = in[i];
        v.x = tanhf(v.x); v.y = tanhf(v.y); v.z = tanhf(v.z); v.w = tanhf(v.w);
        out[i] = v;
    }
}

extern "C" void kernel_launch(void* const* d_in, const int* in_sizes, int n_in,
                              void* d_out, int out_size)
{
    (void)in_sizes; (void)n_in; (void)out_size;
    const float* state = (const float*)d_in[0];
    const float* Wih   = (const float*)d_in[1];   // [2][256][256]
    const float* Whh   = (const float*)d_in[2];   // [2][256][256]
    const float* bih   = (const float*)d_in[3];   // [2][256]
    const float* bhh   = (const float*)d_in[4];   // [2][256]
    const float* W1    = (const float*)d_in[5];   // [1024][320]
    const float* b1    = (const float*)d_in[6];
    const float* W2    = (const float*)d_in[7];   // [1024][1024]
    const float* b2    = (const float*)d_in[8];
    const float* W3    = (const float*)d_in[9];   // [64][1024]
    const float* b3    = (const float*)d_in[10];
    float* out = (float*)d_out;

    float *pU = nullptr, *pY = nullptr, *pH1 = nullptr, *pH2 = nullptr;
    cudaGetSymbolAddress((void**)&pU,  g_U);
    cudaGetSymbolAddress((void**)&pY,  g_Y);
    cudaGetSymbolAddress((void**)&pH1, g_h1);
    cudaGetSymbolAddress((void**)&pH2, g_h2);

    const int BH = B_TOT * H_DIM;   // one timestep slab (16384*256)

    // ---------- RNN layer 0 ----------
    // U[t,b,:] = state_frame(4-t)[b,:] @ Wih0^T + bih0 + bhh0   (all 5 steps batched)
    gemm_nt<128,128,16,A_STATE,E_BIAS><<<dim3(H_DIM/128, (T_STEPS*B_TOT)/128), 256>>>(
        state, 0, nullptr, Wih, bih, bhh, nullptr, pU, T_STEPS*B_TOT, H_DIM, H_DIM);
    // step 0: h = tanh(U[0])
    tanh_ew4<<<(BH/4 + 255)/256, 256>>>((const float4*)pU, (float4*)pY, BH/4);
    // steps 1..4: Y[t] = tanh(Y[t-1] @ Whh0^T + U[t])
    for (int t = 1; t < T_STEPS; ++t) {
        gemm_nt<128,128,16,A_PLAIN,E_ADDU_TANH><<<dim3(H_DIM/128, B_TOT/128), 256>>>(
            pY + (size_t)(t-1)*BH, H_DIM, nullptr, Whh, nullptr, nullptr,
            pU + (size_t)t*BH, pY + (size_t)t*BH, B_TOT, H_DIM, H_DIM);
    }

    // ---------- RNN layer 1 ----------
    // U[t,b,:] = Y0[t,b,:] @ Wih1^T + bih1 + bhh1   (batched over t)
    gemm_nt<128,128,16,A_PLAIN,E_BIAS><<<dim3(H_DIM/128, (T_STEPS*B_TOT)/128), 256>>>(
        pY, H_DIM, nullptr, Wih + H_DIM*H_DIM, bih + H_DIM, bhh + H_DIM, nullptr,
        pU, T_STEPS*B_TOT, H_DIM, H_DIM);
    tanh_ew4<<<(BH/4 + 255)/256, 256>>>((const float4*)pU, (float4*)pY, BH/4);
    for (int t = 1; t < T_STEPS; ++t) {
        gemm_nt<128,128,16,A_PLAIN,E_ADDU_TANH><<<dim3(H_DIM/128, B_TOT/128), 256>>>(
            pY + (size_t)(t-1)*BH, H_DIM, nullptr, Whh + H_DIM*H_DIM, nullptr, nullptr,
            pU + (size_t)t*BH, pY + (size_t)t*BH, B_TOT, H_DIM, H_DIM);
    }
    const float* hn = pY + (size_t)(T_STEPS-1)*BH;   // final hidden of layer 1

    // ---------- MLP ----------
    // h1 = relu([hn, goal] @ W1^T + b1),  K = 256 + 64 = 320
    gemm_nt<128,128,16,A_CONCAT,E_BIAS_RELU><<<dim3(HID_D/128, B_TOT/128), 256>>>(
        hn, H_DIM, state + OBS_D, W1, b1, nullptr, nullptr, pH1, B_TOT, HID_D, H_DIM + GOAL_D);
    // h2 = relu(h1 @ W2^T + b2)
    gemm_nt<128,128,16,A_PLAIN,E_BIAS_RELU><<<dim3(HID_D/128, B_TOT/128), 256>>>(
        pH1, HID_D, nullptr, W2, b2, nullptr, nullptr, pH2, B_TOT, HID_D, HID_D);
    // out = tanh(h2 @ W3^T + b3)
    gemm_nt<128,64,16,A_PLAIN,E_BIAS_TANH><<<dim3(OUT_D/64, B_TOT/128), 256>>>(
        pH2, HID_D, nullptr, W3, b3, nullptr, nullptr, out, B_TOT, OUT_D, HID_D);
}

// round 5
// speedup vs baseline: 1.6205x; 1.6205x over previous
#include <cuda_runtime.h>
#include <cuda_bf16.h>
#include <cstdint>
#include <math.h>

using bf16 = __nv_bfloat16;

// ---------------- problem constants ----------------
#define B_TOT    16384
#define T_STEPS  5
#define H_DIM    256
#define GOAL_D   64
#define HID_D    1024
#define OUT_D    64
#define OBS_D    1280
#define SDIM     1344
#define BH_SLAB  (B_TOT * H_DIM)

// ---------------- device scratch (allocation-free) ----------------
__device__ bf16 g_XH[T_STEPS * B_TOT * H_DIM];
__device__ bf16 g_XL[T_STEPS * B_TOT * H_DIM];
__device__ float g_U[T_STEPS * B_TOT * H_DIM];
__device__ bf16 g_YH[T_STEPS * B_TOT * H_DIM];
__device__ bf16 g_YL[T_STEPS * B_TOT * H_DIM];
__device__ bf16 g_GH[B_TOT * GOAL_D];
__device__ bf16 g_GL[B_TOT * GOAL_D];
__device__ bf16 g_h1H[B_TOT * HID_D];
__device__ bf16 g_h1L[B_TOT * HID_D];
__device__ bf16 g_h2H[B_TOT * HID_D];
__device__ bf16 g_h2L[B_TOT * HID_D];
__device__ bf16 g_WihH[2 * H_DIM * H_DIM], g_WihL[2 * H_DIM * H_DIM];
__device__ bf16 g_WhhH[2 * H_DIM * H_DIM], g_WhhL[2 * H_DIM * H_DIM];
__device__ bf16 g_W1H[HID_D * (H_DIM + GOAL_D)], g_W1L[HID_D * (H_DIM + GOAL_D)];
__device__ bf16 g_W2H[HID_D * HID_D], g_W2L[HID_D * HID_D];
__device__ bf16 g_W3H[OUT_D * HID_D], g_W3L[OUT_D * HID_D];

// ---------------- helpers ----------------
__device__ __forceinline__ void split1(float x, bf16& h, bf16& l) {
    h = __float2bfloat16_rn(x);
    l = __float2bfloat16_rn(x - __bfloat162float(h));
}

__device__ __forceinline__ void mma16816(float* c, const uint32_t* a, const uint32_t* b) {
    asm volatile(
        "mma.sync.aligned.m16n8k16.row.col.f32.bf16.bf16.f32 "
        "{%0,%1,%2,%3}, {%4,%5,%6,%7}, {%8,%9}, {%0,%1,%2,%3};"
        : "+f"(c[0]), "+f"(c[1]), "+f"(c[2]), "+f"(c[3])
        : "r"(a[0]), "r"(a[1]), "r"(a[2]), "r"(a[3]), "r"(b[0]), "r"(b[1]));
}

// ---------------- prep kernels ----------------
__global__ void k_split(const float* __restrict__ s, bf16* __restrict__ h,
                        bf16* __restrict__ l, int n4) {
    int i = blockIdx.x * blockDim.x + threadIdx.x;
    if (i >= n4) return;
    float4 v = ((const float4*)s)[i];
    bf16 h0,h1,h2,h3,l0,l1,l2,l3;
    split1(v.x,h0,l0); split1(v.y,h1,l1); split1(v.z,h2,l2); split1(v.w,h3,l3);
    __nv_bfloat162 a{h0,h1}, b{h2,h3}, c{l0,l1}, d{l2,l3};
    ((uint2*)h)[i] = make_uint2(*(uint32_t*)&a, *(uint32_t*)&b);
    ((uint2*)l)[i] = make_uint2(*(uint32_t*)&c, *(uint32_t*)&d);
}

__global__ void k_split_state(const float* __restrict__ state,
                              bf16* __restrict__ Xh, bf16* __restrict__ Xl) {
    long long i = (long long)blockIdx.x * blockDim.x + threadIdx.x;
    if (i >= (long long)T_STEPS * B_TOT * 64) return;
    int m = (int)(i >> 6), c4 = (int)(i & 63);
    int b = m & (B_TOT - 1), t = m >> 14;
    float4 v = *(const float4*)(state + (long long)b * SDIM + (4 - t) * H_DIM + c4 * 4);
    bf16 h0,h1,h2,h3,l0,l1,l2,l3;
    split1(v.x,h0,l0); split1(v.y,h1,l1); split1(v.z,h2,l2); split1(v.w,h3,l3);
    __nv_bfloat162 a{h0,h1}, bb{h2,h3}, c{l0,l1}, d{l2,l3};
    ((uint2*)(Xh + (long long)m * H_DIM))[c4] = make_uint2(*(uint32_t*)&a, *(uint32_t*)&bb);
    ((uint2*)(Xl + (long long)m * H_DIM))[c4] = make_uint2(*(uint32_t*)&c, *(uint32_t*)&d);
}

__global__ void k_split_goal(const float* __restrict__ state,
                             bf16* __restrict__ Gh, bf16* __restrict__ Gl) {
    int i = blockIdx.x * blockDim.x + threadIdx.x;
    if (i >= B_TOT * 16) return;
    int b = i >> 4, c4 = i & 15;
    float4 v = *(const float4*)(state + (long long)b * SDIM + OBS_D + c4 * 4);
    bf16 h0,h1,h2,h3,l0,l1,l2,l3;
    split1(v.x,h0,l0); split1(v.y,h1,l1); split1(v.z,h2,l2); split1(v.w,h3,l3);
    __nv_bfloat162 a{h0,h1}, bb{h2,h3}, c{l0,l1}, d{l2,l3};
    ((uint2*)(Gh + (long long)b * GOAL_D))[c4] = make_uint2(*(uint32_t*)&a, *(uint32_t*)&bb);
    ((uint2*)(Gl + (long long)b * GOAL_D))[c4] = make_uint2(*(uint32_t*)&c, *(uint32_t*)&d);
}

__global__ void k_tanh_split(const float* __restrict__ u,
                             bf16* __restrict__ Yh, bf16* __restrict__ Yl, int n4) {
    int i = blockIdx.x * blockDim.x + threadIdx.x;
    if (i >= n4) return;
    float4 v = ((const float4*)u)[i];
    v.x = tanhf(v.x); v.y = tanhf(v.y); v.z = tanhf(v.z); v.w = tanhf(v.w);
    bf16 h0,h1,h2,h3,l0,l1,l2,l3;
    split1(v.x,h0,l0); split1(v.y,h1,l1); split1(v.z,h2,l2); split1(v.w,h3,l3);
    __nv_bfloat162 a{h0,h1}, b{h2,h3}, c{l0,l1}, d{l2,l3};
    ((uint2*)Yh)[i] = make_uint2(*(uint32_t*)&a, *(uint32_t*)&b);
    ((uint2*)Yl)[i] = make_uint2(*(uint32_t*)&c, *(uint32_t*)&d);
}

// ---------------- HMMA GEMM (bf16x3 emulated fp32) ----------------
// C[m,n] = epi( sum_k A[m,k]*B[n,k] ),  A = Ah+Al, B = Bh+Bl
// EPI: 0 = +bias1+bias2 -> fp32 ; 1 = +Uadd,tanh -> bf16 hi/lo ;
//      2 = +bias1,relu -> bf16 hi/lo ; 3 = +bias1,tanh -> fp32
// AMODE: 0 plain ; 1 concat (k >= lda pulls from A2, lda2 = GOAL_D)
// CTA 128 x BN, K-chunk 32, 8 warps. Single smem stage (static, <=48KB),
// register-prefetch pipelining across k-chunks.
template<int BN, int AMODE, int EPI>
__global__ __launch_bounds__(256)
void hm_gemm(const bf16* __restrict__ Ah, const bf16* __restrict__ Al, int lda,
             const bf16* __restrict__ A2h, const bf16* __restrict__ A2l,
             const bf16* __restrict__ Bh, const bf16* __restrict__ Bl, int ldb,
             const float* __restrict__ bias1, const float* __restrict__ bias2,
             const float* __restrict__ Uadd,
             float* __restrict__ Cf, bf16* __restrict__ Ch, bf16* __restrict__ Cl,
             int K, int Ntot)
{
    constexpr int MT = (BN == 128) ? 4 : 2;     // m16 tiles per warp
    constexpr int NT = 4;                       // n8 tiles per warp (warp N = 32)
    constexpr int ASZ = 128 * 40;               // bf16 elems per A buffer
    constexpr int BSZ = BN * 40;
    constexpr int AW  = ASZ / 2;                // words
    constexpr int BW  = BSZ / 2;

    __shared__ __align__(16) bf16 sm[2 * ASZ + 2 * BSZ];   // 40KB (BN=128) / 30KB (BN=64)

    const int tid = threadIdx.x;
    const int wid = tid >> 5, lane = tid & 31;
    const int m0 = blockIdx.y * 128, n0 = blockIdx.x * BN;
    const int wm = (BN == 128) ? (wid & 1) * 64 : (wid & 3) * 32;
    const int wn = (BN == 128) ? (wid >> 1) * 32 : (wid >> 2) * 32;
    const int lr = tid >> 2;     // loader row 0..63
    const int lc = tid & 3;      // loader 16B chunk

    float acc[MT][NT][4];
#pragma unroll
    for (int i = 0; i < MT; ++i)
#pragma unroll
        for (int j = 0; j < NT; ++j)
#pragma unroll
            for (int q = 0; q < 4; ++q) acc[i][j][q] = 0.0f;

    const int nkt = K >> 5;
    uint4 pAh[2], pAl[2], pBh[2], pBl[2];

    auto gload = [&](int kb) {
        const bf16 *aH = Ah, *aL = Al;
        int alda = lda, acol = kb;
        if (AMODE == 1 && kb >= lda) { aH = A2h; aL = A2l; alda = GOAL_D; acol = kb - lda; }
#pragma unroll
        for (int j = 0; j < 2; ++j) {
            int r = lr + j * 64;
            long long go = (long long)(m0 + r) * alda + acol + lc * 8;
            pAh[j] = *(const uint4*)(aH + go);
            pAl[j] = *(const uint4*)(aL + go);
        }
#pragma unroll
        for (int j = 0; j < BN / 64; ++j) {
            int r = lr + j * 64;
            long long go = (long long)(n0 + r) * ldb + kb + lc * 8;
            pBh[j] = *(const uint4*)(Bh + go);
            pBl[j] = *(const uint4*)(Bl + go);
        }
    };
    auto sstore = [&]() {
#pragma unroll
        for (int j = 0; j < 2; ++j) {
            int r = lr + j * 64;
            *(uint4*)(sm + r * 40 + lc * 8) = pAh[j];
            *(uint4*)(sm + ASZ + r * 40 + lc * 8) = pAl[j];
        }
#pragma unroll
        for (int j = 0; j < BN / 64; ++j) {
            int r = lr + j * 64;
            *(uint4*)(sm + 2 * ASZ + r * 40 + lc * 8) = pBh[j];
            *(uint4*)(sm + 2 * ASZ + BSZ + r * 40 + lc * 8) = pBl[j];
        }
    };
    auto compute = [&]() {
        const uint32_t* base = (const uint32_t*)sm;
        const uint32_t* sAh = base;
        const uint32_t* sAl = base + AW;
        const uint32_t* sBh = base + 2 * AW;
        const uint32_t* sBl = base + 2 * AW + BW;
#pragma unroll
        for (int k16 = 0; k16 < 2; ++k16) {
            const int cw = k16 * 8 + (lane & 3);
            uint32_t ah[MT][4], al[MT][4], bh[NT][2], bl[NT][2];
#pragma unroll
            for (int mt = 0; mt < MT; ++mt) {
                int r0 = (wm + mt * 16 + (lane >> 2)) * 20;
                ah[mt][0] = sAh[r0 + cw];       ah[mt][1] = sAh[r0 + 160 + cw];
                ah[mt][2] = sAh[r0 + cw + 4];   ah[mt][3] = sAh[r0 + 160 + cw + 4];
                al[mt][0] = sAl[r0 + cw];       al[mt][1] = sAl[r0 + 160 + cw];
                al[mt][2] = sAl[r0 + cw + 4];   al[mt][3] = sAl[r0 + 160 + cw + 4];
            }
#pragma unroll
            for (int nt = 0; nt < NT; ++nt) {
                int r0 = (wn + nt * 8 + (lane >> 2)) * 20;
                bh[nt][0] = sBh[r0 + cw];  bh[nt][1] = sBh[r0 + cw + 4];
                bl[nt][0] = sBl[r0 + cw];  bl[nt][1] = sBl[r0 + cw + 4];
            }
#pragma unroll
            for (int mt = 0; mt < MT; ++mt)
#pragma unroll
                for (int nt = 0; nt < NT; ++nt) mma16816(acc[mt][nt], ah[mt], bh[nt]);
#pragma unroll
            for (int mt = 0; mt < MT; ++mt)
#pragma unroll
                for (int nt = 0; nt < NT; ++nt) mma16816(acc[mt][nt], ah[mt], bl[nt]);
#pragma unroll
            for (int mt = 0; mt < MT; ++mt)
#pragma unroll
                for (int nt = 0; nt < NT; ++nt) mma16816(acc[mt][nt], al[mt], bh[nt]);
        }
    };

    gload(0);
    sstore();
    __syncthreads();
    for (int kt = 0; kt < nkt; ++kt) {
        if (kt + 1 < nkt) gload((kt + 1) * 32);   // prefetch into registers
        compute();
        __syncthreads();                           // everyone done reading stage
        if (kt + 1 < nkt) {
            sstore();
            __syncthreads();                       // stage refilled
        }
    }

    // ---- epilogue ----
#pragma unroll
    for (int mt = 0; mt < MT; ++mt) {
#pragma unroll
        for (int nt = 0; nt < NT; ++nt) {
            const int ncol = n0 + wn + nt * 8 + (lane & 3) * 2;
#pragma unroll
            for (int h = 0; h < 2; ++h) {
                const int m = m0 + wm + mt * 16 + (lane >> 2) + h * 8;
                float x = acc[mt][nt][h * 2 + 0];
                float y = acc[mt][nt][h * 2 + 1];
                if (EPI == 0) {
                    float2 b = *(const float2*)(bias1 + ncol);
                    float2 c = *(const float2*)(bias2 + ncol);
                    float2 o{ x + b.x + c.x, y + b.y + c.y };
                    *(float2*)(Cf + (long long)m * Ntot + ncol) = o;
                } else if (EPI == 3) {
                    float2 b = *(const float2*)(bias1 + ncol);
                    float2 o{ tanhf(x + b.x), tanhf(y + b.y) };
                    *(float2*)(Cf + (long long)m * Ntot + ncol) = o;
                } else {
                    if (EPI == 1) {
                        float2 u = *(const float2*)(Uadd + (long long)m * Ntot + ncol);
                        x = tanhf(x + u.x); y = tanhf(y + u.y);
                    } else {
                        float2 b = *(const float2*)(bias1 + ncol);
                        x = fmaxf(x + b.x, 0.0f); y = fmaxf(y + b.y, 0.0f);
                    }
                    bf16 hx, lx, hy, ly;
                    split1(x, hx, lx); split1(y, hy, ly);
                    __nv_bfloat162 hp{hx, hy}, lp{lx, ly};
                    *(uint32_t*)(Ch + (long long)m * Ntot + ncol) = *(uint32_t*)&hp;
                    *(uint32_t*)(Cl + (long long)m * Ntot + ncol) = *(uint32_t*)&lp;
                }
            }
        }
    }
}

// ---------------- host ----------------
static inline int gsz(int n, int b) { return (n + b - 1) / b; }

extern "C" void kernel_launch(void* const* d_in, const int* in_sizes, int n_in,
                              void* d_out, int out_size)
{
    (void)in_sizes; (void)n_in; (void)out_size;
    const float* state = (const float*)d_in[0];
    const float* Wih   = (const float*)d_in[1];
    const float* Whh   = (const float*)d_in[2];
    const float* bih   = (const float*)d_in[3];
    const float* bhh   = (const float*)d_in[4];
    const float* W1    = (const float*)d_in[5];
    const float* b1    = (const float*)d_in[6];
    const float* W2    = (const float*)d_in[7];
    const float* b2    = (const float*)d_in[8];
    const float* W3    = (const float*)d_in[9];
    const float* b3    = (const float*)d_in[10];
    float* out = (float*)d_out;

    bf16 *XH,*XL,*YH,*YL,*GH,*GL,*h1H,*h1L,*h2H,*h2L;
    bf16 *WihH,*WihL,*WhhH,*WhhL,*W1H,*W1L,*W2H,*W2L,*W3H,*W3L;
    float* U;
    cudaGetSymbolAddress((void**)&XH, g_XH);   cudaGetSymbolAddress((void**)&XL, g_XL);
    cudaGetSymbolAddress((void**)&YH, g_YH);   cudaGetSymbolAddress((void**)&YL, g_YL);
    cudaGetSymbolAddress((void**)&GH, g_GH);   cudaGetSymbolAddress((void**)&GL, g_GL);
    cudaGetSymbolAddress((void**)&h1H, g_h1H); cudaGetSymbolAddress((void**)&h1L, g_h1L);
    cudaGetSymbolAddress((void**)&h2H, g_h2H); cudaGetSymbolAddress((void**)&h2L, g_h2L);
    cudaGetSymbolAddress((void**)&WihH, g_WihH); cudaGetSymbolAddress((void**)&WihL, g_WihL);
    cudaGetSymbolAddress((void**)&WhhH, g_WhhH); cudaGetSymbolAddress((void**)&WhhL, g_WhhL);
    cudaGetSymbolAddress((void**)&W1H, g_W1H);   cudaGetSymbolAddress((void**)&W1L, g_W1L);
    cudaGetSymbolAddress((void**)&W2H, g_W2H);   cudaGetSymbolAddress((void**)&W2L, g_W2L);
    cudaGetSymbolAddress((void**)&W3H, g_W3H);   cudaGetSymbolAddress((void**)&W3L, g_W3L);
    cudaGetSymbolAddress((void**)&U, g_U);

    // ---- prep ----
    k_split<<<gsz(2*H_DIM*H_DIM/4,256),256>>>(Wih, WihH, WihL, 2*H_DIM*H_DIM/4);
    k_split<<<gsz(2*H_DIM*H_DIM/4,256),256>>>(Whh, WhhH, WhhL, 2*H_DIM*H_DIM/4);
    k_split<<<gsz(HID_D*(H_DIM+GOAL_D)/4,256),256>>>(W1, W1H, W1L, HID_D*(H_DIM+GOAL_D)/4);
    k_split<<<gsz(HID_D*HID_D/4,256),256>>>(W2, W2H, W2L, HID_D*HID_D/4);
    k_split<<<gsz(OUT_D*HID_D/4,256),256>>>(W3, W3H, W3L, OUT_D*HID_D/4);
    k_split_state<<<gsz(T_STEPS*B_TOT*64,256),256>>>(state, XH, XL);
    k_split_goal<<<gsz(B_TOT*16,256),256>>>(state, GH, GL);

    // ---- RNN layer 0 ----
    hm_gemm<128,0,0><<<dim3(2, T_STEPS*B_TOT/128), 256>>>(
        XH, XL, H_DIM, nullptr, nullptr, WihH, WihL, H_DIM,
        bih, bhh, nullptr, U, nullptr, nullptr, H_DIM, H_DIM);
    k_tanh_split<<<gsz(BH_SLAB/4,256),256>>>(U, YH, YL, BH_SLAB/4);
    for (int t = 1; t < T_STEPS; ++t) {
        hm_gemm<128,0,1><<<dim3(2, B_TOT/128), 256>>>(
            YH + (long long)(t-1)*BH_SLAB, YL + (long long)(t-1)*BH_SLAB, H_DIM,
            nullptr, nullptr, WhhH, WhhL, H_DIM,
            nullptr, nullptr, U + (long long)t*BH_SLAB,
            nullptr, YH + (long long)t*BH_SLAB, YL + (long long)t*BH_SLAB, H_DIM, H_DIM);
    }

    // ---- RNN layer 1 ----
    hm_gemm<128,0,0><<<dim3(2, T_STEPS*B_TOT/128), 256>>>(
        YH, YL, H_DIM, nullptr, nullptr,
        WihH + H_DIM*H_DIM, WihL + H_DIM*H_DIM, H_DIM,
        bih + H_DIM, bhh + H_DIM, nullptr, U, nullptr, nullptr, H_DIM, H_DIM);
    k_tanh_split<<<gsz(BH_SLAB/4,256),256>>>(U, YH, YL, BH_SLAB/4);
    for (int t = 1; t < T_STEPS; ++t) {
        hm_gemm<128,0,1><<<dim3(2, B_TOT/128), 256>>>(
            YH + (long long)(t-1)*BH_SLAB, YL + (long long)(t-1)*BH_SLAB, H_DIM,
            nullptr, nullptr, WhhH + H_DIM*H_DIM, WhhL + H_DIM*H_DIM, H_DIM,
            nullptr, nullptr, U + (long long)t*BH_SLAB,
            nullptr, YH + (long long)t*BH_SLAB, YL + (long long)t*BH_SLAB, H_DIM, H_DIM);
    }
    const bf16* hnH = YH + (long long)(T_STEPS-1)*BH_SLAB;
    const bf16* hnL = YL + (long long)(T_STEPS-1)*BH_SLAB;

    // ---- MLP ----
    hm_gemm<128,1,2><<<dim3(HID_D/128, B_TOT/128), 256>>>(
        hnH, hnL, H_DIM, GH, GL, W1H, W1L, H_DIM + GOAL_D,
        b1, nullptr, nullptr, nullptr, h1H, h1L, H_DIM + GOAL_D, HID_D);
    hm_gemm<128,0,2><<<dim3(HID_D/128, B_TOT/128), 256>>>(
        h1H, h1L, HID_D, nullptr, nullptr, W2H, W2L, HID_D,
        b2, nullptr, nullptr, nullptr, h2H, h2L, HID_D, HID_D);
    hm_gemm<64,0,3><<<dim3(1, B_TOT/128), 256>>>(
        h2H, h2L, HID_D, nullptr, nullptr, W3H, W3L, HID_D,
        b3, nullptr, nullptr, out, nullptr, nullptr, HID_D, OUT_D);
}